// round 17
// baseline (speedup 1.0000x reference)
#include <cuda_runtime.h>
#include <cuda_bf16.h>
#include <stdint.h>

#define D_MODEL 4096
#define SHARDS  8
#define N_VOCAB 50400

// Single kernel, single launch, no sync. One token row per CTA (grid=T),
// 256 threads x 4 float4 = 4096 floats per row. Bias is recomputed per thread
// from b directly: b is 32 KB -> L1/L2 resident, so the 8-shard reduction is
// 32 cache-hit loads + 32 FADDs per thread, hidden under the DRAM-latency-
// bound W gather. This deletes the prologue kernel, the PDL node, and all
// device-global scratch/fencing.
__global__ __launch_bounds__(256) void embed_fused_kernel(
    const void* __restrict__ tok,        // [T] int32 or int64 ids
    const float* __restrict__ b,         // [SHARDS, D_MODEL]
    const float* __restrict__ W,         // [N_VOCAB, D_MODEL]
    float* __restrict__ out)             // [T, D_MODEL]
{
    const int t = blockIdx.x;
    const int tid = threadIdx.x;

    // Local dtype detection: for int64 ids (< 50400 << 2^31) every odd 32-bit
    // word of the buffer is 0; for int32 ids the odd words are random tokens
    // (all-zero probability ~ (1/50400)^4). Two 16B loads, L2-resident.
    const int4* tq = (const int4*)tok;
    int4 q0 = tq[0], q1 = tq[1];
    const bool is64 = ((q0.y | q0.w | q1.y | q1.w) == 0);

    long long id = is64 ? ((const long long*)tok)[t]
                        : (long long)((const int*)tok)[t];
    // Clamp defensively: OOB would hard-fault; wrong-but-inbounds fails
    // rel_err instead, which is diagnosable.
    if (id < 0) id = 0;
    if (id >= N_VOCAB) id = N_VOCAB - 1;

    const float4* __restrict__ wrow = reinterpret_cast<const float4*>(W + (size_t)id * D_MODEL);
    const float4* __restrict__ b4   = reinterpret_cast<const float4*>(b);
    float4* __restrict__ orow       = reinterpret_cast<float4*>(out + (size_t)t * D_MODEL);

    // Issue all 4 W loads up front (streaming: W is 206 MB, no reuse to speak of).
    float4 a[4];
#pragma unroll
    for (int i = 0; i < 4; i++) a[i] = __ldcs(&wrow[tid + i * 256]);

    // Per column-group: reduce b over shards (L1-hot), add to W row, store.
    // Interleaved to keep register pressure low (one accumulator live).
#pragma unroll
    for (int i = 0; i < 4; i++) {
        const int col4 = tid + i * 256;               // float4 index in [0,1024)
        float4 s = __ldg(&b4[col4]);                  // shard 0
#pragma unroll
        for (int k = 1; k < SHARDS; k++) {
            float4 v = __ldg(&b4[k * (D_MODEL / 4) + col4]);
            s.x += v.x; s.y += v.y; s.z += v.z; s.w += v.w;
        }
        float4 r = a[i];
        r.x += s.x; r.y += s.y; r.z += s.z; r.w += s.w;
        __stcs(&orow[col4], r);
    }
}

extern "C" void kernel_launch(void* const* d_in, const int* in_sizes, int n_in,
                              void* d_out, int out_size) {
    // Identify inputs by element count, independent of metadata order.
    const void* tok = nullptr;
    const float* W = nullptr;
    const float* b = nullptr;
    for (int i = 0; i < n_in; i++) {
        long long sz = in_sizes[i];
        if (sz > 100000000LL)            W   = (const float*)d_in[i];  // 50400*4096
        else if (sz == SHARDS * D_MODEL) b   = (const float*)d_in[i];  // 32768
        else                             tok = d_in[i];                // token ids
    }

    float* out = (float*)d_out;               // [T, D_MODEL]
    const int T = out_size / D_MODEL;         // 4096

    embed_fused_kernel<<<T, 256>>>(tok, b, W, out);
}